// round 3
// baseline (speedup 1.0000x reference)
#include <cuda_runtime.h>

#define NN 8192
#define DD 512
#define LSCALE 2.659f

// Scratch (device globals — no allocation allowed in kernel_launch)
__device__ __align__(128) float g_A[NN * DD];   // normalized image features
__device__ __align__(128) float g_B[NN * DD];   // normalized text features
__device__ float g_rowE[NN], g_rowW[NN], g_colE[NN], g_colW[NN];
__device__ float g_Sinv[NN];
__device__ int   g_lab[NN];
__device__ int   g_hist[128];

// ---------------------------------------------------------------------------
__global__ void k_init() {
    int i = blockIdx.x * blockDim.x + threadIdx.x;
    if (i < NN) { g_rowE[i] = 0.f; g_rowW[i] = 0.f; g_colE[i] = 0.f; g_colW[i] = 0.f; }
    if (i < 128) g_hist[i] = 0;
}

// One block per row (2N blocks): L2-normalize into g_A / g_B.
__global__ void k_norm(const float* __restrict__ txt, const float* __restrict__ img) {
    int b = blockIdx.x;
    const float* src;
    float* dst;
    if (b < NN) { src = img + (size_t)b * DD; dst = g_A + (size_t)b * DD; }
    else        { src = txt + (size_t)(b - NN) * DD; dst = g_B + (size_t)(b - NN) * DD; }
    int t = threadIdx.x;  // 128 threads, 4 floats each
    float4 v = ((const float4*)src)[t];
    float ss = v.x * v.x + v.y * v.y + v.z * v.z + v.w * v.w;
    #pragma unroll
    for (int m = 16; m; m >>= 1) ss += __shfl_xor_sync(0xffffffffu, ss, m);
    __shared__ float sp[4];
    if ((t & 31) == 0) sp[t >> 5] = ss;
    __syncthreads();
    float tot = sp[0] + sp[1] + sp[2] + sp[3];
    float inv = 1.0f / fmaxf(sqrtf(tot), 1e-12f);
    v.x *= inv; v.y *= inv; v.z *= inv; v.w *= inv;
    ((float4*)dst)[t] = v;
}

// labels arrive as int32 (JAX x64 disabled downcasts jnp.int64 -> int32).
__global__ void k_lab(const int* __restrict__ labels) {
    int i = blockIdx.x * blockDim.x + threadIdx.x;
    if (i < NN) {
        int l = labels[i];
        if (l < -1 || l >= 128) l = -1;   // defensive clamp
        g_lab[i] = l;
        if (l >= 0) atomicAdd(&g_hist[l], 1);
    }
}

__global__ void k_S() {
    int i = blockIdx.x * blockDim.x + threadIdx.x;
    if (i < NN) {
        int l = g_lab[i];
        g_Sinv[i] = (l < 0) ? 1.0f : 1.0f / (float)g_hist[l];
    }
}

// ---------------------------------------------------------------------------
// Fused GEMM + soft-CE epilogue.
// C[i,j] = LSCALE * dot(img_i, txt_j). Per tile, accumulate:
//   row: sum_j exp(C - LSCALE), sum_j T[i,j]*C     (image direction)
//   col: sum_i exp(C - LSCALE), sum_i T[i,j]*C     (text direction)
// 128x128 tile, BK=16, 256 threads, 8x8 per thread.
__global__ __launch_bounds__(256, 2) void k_gemm() {
    __shared__ __align__(16) float As[16][132];
    __shared__ __align__(16) float Bs[16][132];
    __shared__ float sCE[128], sCW[128];
    __shared__ int sLR[128], sLC[128];

    int tid = threadIdx.x;
    int bm = blockIdx.y * 128, bn = blockIdx.x * 128;

    if (tid < 128) {
        sCE[tid] = 0.f; sCW[tid] = 0.f;
        sLR[tid] = g_lab[bm + tid];
        sLC[tid] = g_lab[bn + tid];
    }

    float acc[8][8];
    #pragma unroll
    for (int i = 0; i < 8; i++)
        #pragma unroll
        for (int j = 0; j < 8; j++) acc[i][j] = 0.f;

    const float* Ag = g_A + (size_t)bm * DD;
    const float* Bg = g_B + (size_t)bn * DD;
    int lr = tid >> 2;
    int lc = (tid & 3) << 2;
    int ty = tid >> 4, tx = tid & 15;
    int rowBase = ty * 8, colBase = tx * 8;

    for (int k0 = 0; k0 < DD; k0 += 16) {
        float4 a0 = *(const float4*)(Ag + (size_t)lr * DD + k0 + lc);
        float4 a1 = *(const float4*)(Ag + (size_t)(lr + 64) * DD + k0 + lc);
        float4 b0 = *(const float4*)(Bg + (size_t)lr * DD + k0 + lc);
        float4 b1 = *(const float4*)(Bg + (size_t)(lr + 64) * DD + k0 + lc);
        __syncthreads();
        As[lc + 0][lr] = a0.x; As[lc + 1][lr] = a0.y; As[lc + 2][lr] = a0.z; As[lc + 3][lr] = a0.w;
        As[lc + 0][lr + 64] = a1.x; As[lc + 1][lr + 64] = a1.y; As[lc + 2][lr + 64] = a1.z; As[lc + 3][lr + 64] = a1.w;
        Bs[lc + 0][lr] = b0.x; Bs[lc + 1][lr] = b0.y; Bs[lc + 2][lr] = b0.z; Bs[lc + 3][lr] = b0.w;
        Bs[lc + 0][lr + 64] = b1.x; Bs[lc + 1][lr + 64] = b1.y; Bs[lc + 2][lr + 64] = b1.z; Bs[lc + 3][lr + 64] = b1.w;
        __syncthreads();
        #pragma unroll
        for (int k = 0; k < 16; k++) {
            float a[8], b[8];
            float4 av0 = *(const float4*)&As[k][rowBase];
            float4 av1 = *(const float4*)&As[k][rowBase + 4];
            float4 bv0 = *(const float4*)&Bs[k][colBase];
            float4 bv1 = *(const float4*)&Bs[k][colBase + 4];
            a[0] = av0.x; a[1] = av0.y; a[2] = av0.z; a[3] = av0.w;
            a[4] = av1.x; a[5] = av1.y; a[6] = av1.z; a[7] = av1.w;
            b[0] = bv0.x; b[1] = bv0.y; b[2] = bv0.z; b[3] = bv0.w;
            b[4] = bv1.x; b[5] = bv1.y; b[6] = bv1.z; b[7] = bv1.w;
            #pragma unroll
            for (int i = 0; i < 8; i++)
                #pragma unroll
                for (int j = 0; j < 8; j++)
                    acc[i][j] = fmaf(a[i], b[j], acc[i][j]);
        }
    }

    // ---- fused epilogue ----
    float rE[8], rW[8], cE[8], cW[8];
    #pragma unroll
    for (int i = 0; i < 8; i++) { rE[i] = 0.f; rW[i] = 0.f; cE[i] = 0.f; cW[i] = 0.f; }

    #pragma unroll
    for (int i = 0; i < 8; i++) {
        int li = sLR[rowBase + i];
        int gi = bm + rowBase + i;
        #pragma unroll
        for (int j = 0; j < 8; j++) {
            float l = acc[i][j] * LSCALE;
            float e = __expf(l - LSCALE);          // shift by bound, no max pass
            rE[i] += e; cE[j] += e;
            int lj = sLC[colBase + j];
            bool t = (gi == bn + colBase + j) || (li >= 0 && li == lj);
            if (t) { rW[i] += l; cW[j] += l; }
        }
    }

    // Row reduce across tx (16 lanes within each half-warp; ty unique per half-warp)
    #pragma unroll
    for (int m = 1; m < 16; m <<= 1) {
        #pragma unroll
        for (int i = 0; i < 8; i++) {
            rE[i] += __shfl_xor_sync(0xffffffffu, rE[i], m);
            rW[i] += __shfl_xor_sync(0xffffffffu, rW[i], m);
        }
    }
    if ((tid & 15) == 0) {
        #pragma unroll
        for (int i = 0; i < 8; i++) {
            atomicAdd(&g_rowE[bm + rowBase + i], rE[i]);
            atomicAdd(&g_rowW[bm + rowBase + i], rW[i]);
        }
    }

    // Col reduce: fold the two ty-halves of the warp (same columns), then shared atomics
    #pragma unroll
    for (int j = 0; j < 8; j++) {
        cE[j] += __shfl_xor_sync(0xffffffffu, cE[j], 16);
        cW[j] += __shfl_xor_sync(0xffffffffu, cW[j], 16);
    }
    if ((tid & 31) < 16) {
        int cb = (tid & 15) * 8;
        #pragma unroll
        for (int j = 0; j < 8; j++) {
            atomicAdd(&sCE[cb + j], cE[j]);
            atomicAdd(&sCW[cb + j], cW[j]);
        }
    }
    __syncthreads();
    if (tid < 128) {
        atomicAdd(&g_colE[bn + tid], sCE[tid]);
        atomicAdd(&g_colW[bn + tid], sCW[tid]);
    }
}

// ---------------------------------------------------------------------------
__global__ void k_final(float* __restrict__ out) {
    int t = threadIdx.x;
    float s = 0.f;
    for (int i = t; i < NN; i += 256) {
        float si = g_Sinv[i];
        float li = logf(g_rowE[i]) + LSCALE - g_rowW[i] * si;   // image direction
        float lt = logf(g_colE[i]) + LSCALE - g_colW[i] * si;   // text direction
        s += 0.5f * (li + lt);
    }
    __shared__ float red[256];
    red[t] = s;
    __syncthreads();
    for (int m = 128; m; m >>= 1) {
        if (t < m) red[t] += red[t + m];
        __syncthreads();
    }
    if (t == 0) out[0] = red[0] / (float)NN;
}

// ---------------------------------------------------------------------------
extern "C" void kernel_launch(void* const* d_in, const int* in_sizes, int n_in,
                              void* d_out, int out_size) {
    const float* txt = (const float*)d_in[0];        // text_features [8192,512] f32
    const float* img = (const float*)d_in[1];        // image_features [8192,512] f32
    const int* labels = (const int*)d_in[2];         // labels [8192] int32
    float* out = (float*)d_out;

    k_init<<<(NN + 255) / 256, 256>>>();
    k_norm<<<2 * NN, 128>>>(txt, img);
    k_lab<<<(NN + 255) / 256, 256>>>(labels);
    k_S<<<(NN + 255) / 256, 256>>>();
    dim3 g(NN / 128, NN / 128);
    k_gemm<<<g, 256>>>();
    k_final<<<1, 256>>>(out);
}

// round 5
// speedup vs baseline: 2.4867x; 2.4867x over previous
#include <cuda_runtime.h>
#include <cuda_bf16.h>
#include <cstdint>

#define NN 8192
#define DD 512
#define LSCALE 2.659f

// ---------------- device scratch ----------------
__device__ __align__(128) __nv_bfloat16 g_Ahi[NN * DD];
__device__ __align__(128) __nv_bfloat16 g_Alo[NN * DD];
__device__ __align__(128) __nv_bfloat16 g_Bhi[NN * DD];
__device__ __align__(128) __nv_bfloat16 g_Blo[NN * DD];
__device__ float g_rowE[NN], g_rowW[NN], g_colE[NN], g_colW[NN];
__device__ float g_Sinv[NN];
__device__ int   g_lab[NN];
__device__ int   g_hist[128];

// ---------------- asm helpers ----------------
__device__ __forceinline__ uint32_t smem_u32(const void* p) {
    uint32_t a;
    asm("{ .reg .u64 t; cvta.to.shared.u64 t, %1; cvt.u32.u64 %0, t; }" : "=r"(a) : "l"(p));
    return a;
}
#define CP_ASYNC16(dst, src) \
    asm volatile("cp.async.cg.shared.global [%0], [%1], 16;" :: "r"(dst), "l"(src) : "memory")
#define CP_COMMIT() asm volatile("cp.async.commit_group;" ::: "memory")
#define CP_WAIT0()  asm volatile("cp.async.wait_group 0;" ::: "memory")

#define LDSM4(r0, r1, r2, r3, addr) \
    asm volatile("ldmatrix.sync.aligned.m8n8.x4.shared.b16 {%0,%1,%2,%3}, [%4];" \
                 : "=r"(r0), "=r"(r1), "=r"(r2), "=r"(r3) : "r"(addr))

#define MMA16816(d, a, b0, b1) \
    asm volatile("mma.sync.aligned.m16n8k16.row.col.f32.bf16.bf16.f32 " \
                 "{%0,%1,%2,%3}, {%4,%5,%6,%7}, {%8,%9}, {%0,%1,%2,%3};" \
                 : "+f"((d)[0]), "+f"((d)[1]), "+f"((d)[2]), "+f"((d)[3]) \
                 : "r"((a)[0]), "r"((a)[1]), "r"((a)[2]), "r"((a)[3]), "r"(b0), "r"(b1))

// smem tile geometry: rows padded 64B -> 80B (bank-conflict-free ldmatrix)
#define PITCH  80
#define TILE_B (128 * PITCH)     // 10240
#define STAGE_B (4 * TILE_B)     // 40960 (Ahi, Alo, Bhi, Blo)
#define SMEM_RED (2 * STAGE_B)
#define SMEM_TOT (2 * STAGE_B + 128 * 4 * 6)  // + sLR,sLC,sRE,sRW,sCE,sCW

// ---------------------------------------------------------------------------
__global__ void k_init() {
    int i = blockIdx.x * blockDim.x + threadIdx.x;
    if (i < NN) { g_rowE[i] = 0.f; g_rowW[i] = 0.f; g_colE[i] = 0.f; g_colW[i] = 0.f; }
    if (i < 128) g_hist[i] = 0;
}

// normalize + split into bf16 hi/lo
__global__ void k_norm(const float* __restrict__ txt, const float* __restrict__ img) {
    int b = blockIdx.x;
    const float* src;
    __nv_bfloat16 *hid, *lod;
    if (b < NN) { src = img + (size_t)b * DD; hid = g_Ahi + (size_t)b * DD; lod = g_Alo + (size_t)b * DD; }
    else { b -= NN; src = txt + (size_t)b * DD; hid = g_Bhi + (size_t)b * DD; lod = g_Blo + (size_t)b * DD; }
    int t = threadIdx.x;
    float4 v = ((const float4*)src)[t];
    float ss = v.x * v.x + v.y * v.y + v.z * v.z + v.w * v.w;
    #pragma unroll
    for (int m = 16; m; m >>= 1) ss += __shfl_xor_sync(0xffffffffu, ss, m);
    __shared__ float sp[4];
    if ((t & 31) == 0) sp[t >> 5] = ss;
    __syncthreads();
    float inv = 1.0f / fmaxf(sqrtf(sp[0] + sp[1] + sp[2] + sp[3]), 1e-12f);
    float x0 = v.x * inv, x1 = v.y * inv, x2 = v.z * inv, x3 = v.w * inv;
    __nv_bfloat16 h0 = __float2bfloat16(x0), h1 = __float2bfloat16(x1);
    __nv_bfloat16 h2 = __float2bfloat16(x2), h3 = __float2bfloat16(x3);
    __nv_bfloat16 l0 = __float2bfloat16(x0 - __bfloat162float(h0));
    __nv_bfloat16 l1 = __float2bfloat16(x1 - __bfloat162float(h1));
    __nv_bfloat16 l2 = __float2bfloat16(x2 - __bfloat162float(h2));
    __nv_bfloat16 l3 = __float2bfloat16(x3 - __bfloat162float(h3));
    __nv_bfloat162* hp = (__nv_bfloat162*)hid;
    __nv_bfloat162* lp = (__nv_bfloat162*)lod;
    hp[t * 2 + 0] = __nv_bfloat162(h0, h1);
    hp[t * 2 + 1] = __nv_bfloat162(h2, h3);
    lp[t * 2 + 0] = __nv_bfloat162(l0, l1);
    lp[t * 2 + 1] = __nv_bfloat162(l2, l3);
}

__global__ void k_lab(const int* __restrict__ labels) {
    int i = blockIdx.x * blockDim.x + threadIdx.x;
    if (i < NN) {
        int l = labels[i];
        if (l < -1 || l >= 128) l = -1;
        g_lab[i] = l;
        if (l >= 0) atomicAdd(&g_hist[l], 1);
    }
}

__global__ void k_S() {
    int i = blockIdx.x * blockDim.x + threadIdx.x;
    if (i < NN) {
        int l = g_lab[i];
        g_Sinv[i] = (l < 0) ? 1.0f : 1.0f / (float)g_hist[l];
    }
}

// ---------------------------------------------------------------------------
// HMMA (mma.sync bf16, hi/lo split x3) GEMM + fused soft-CE epilogue.
// 128x128 tile, 8 warps in 2x4, warp tile 64x32, BK=32, double-buffered cp.async.
__global__ __launch_bounds__(256, 2) void k_gemm_mma() {
    extern __shared__ __align__(16) char smem[];
    uint32_t sb = smem_u32(smem);
    int* sLR = (int*)(smem + SMEM_RED);
    int* sLC = sLR + 128;
    float* sRE = (float*)(sLC + 128);
    float* sRW = sRE + 128;
    float* sCE = sRW + 128;
    float* sCW = sCE + 128;

    int tid = threadIdx.x, lane = tid & 31, wid = tid >> 5;
    int wy = wid >> 2, wx = wid & 3;          // warp grid 2 (m) x 4 (n)
    int gid = lane >> 2, tig = lane & 3;
    int bm = blockIdx.y * 128, bn = blockIdx.x * 128;

    if (tid < 128) {
        sLR[tid] = g_lab[bm + tid]; sLC[tid] = g_lab[bn + tid];
        sRE[tid] = 0.f; sRW[tid] = 0.f; sCE[tid] = 0.f; sCW[tid] = 0.f;
    }

    const __nv_bfloat16* const srcs[4] = {
        g_Ahi + (size_t)bm * DD, g_Alo + (size_t)bm * DD,
        g_Bhi + (size_t)bn * DD, g_Blo + (size_t)bn * DD };

    auto copy_stage = [&](int it) {
        uint32_t dstb = sb + (uint32_t)(it & 1) * STAGE_B;
        int k0 = it * 32;
        #pragma unroll
        for (int a = 0; a < 4; a++) {
            #pragma unroll
            for (int i = 0; i < 2; i++) {
                int idx = tid + 256 * i;         // 0..511
                int row = idx >> 2, c = idx & 3; // 4 x 16B per 64B row
                const __nv_bfloat16* src = srcs[a] + (size_t)row * DD + k0 + c * 8;
                uint32_t dst = dstb + a * TILE_B + row * PITCH + c * 16;
                CP_ASYNC16(dst, src);
            }
        }
        CP_COMMIT();
    };

    float acc[4][4][4];
    #pragma unroll
    for (int mf = 0; mf < 4; mf++)
        #pragma unroll
        for (int nf = 0; nf < 4; nf++)
            #pragma unroll
            for (int e = 0; e < 4; e++) acc[mf][nf][e] = 0.f;

    copy_stage(0);

    // precomputed ldmatrix lane offsets
    int a_row = (lane & 15);
    uint32_t a_koff = (uint32_t)((lane >> 4) << 4);
    int b_nrow = (lane & 7) + ((lane >> 4) << 3);
    uint32_t b_koff = (uint32_t)(((lane >> 3) & 1) << 4);

    for (int it = 0; it < 16; it++) {
        CP_WAIT0();
        __syncthreads();
        if (it < 15) copy_stage(it + 1);
        uint32_t buf = sb + (uint32_t)(it & 1) * STAGE_B;

        #pragma unroll
        for (int kk = 0; kk < 2; kk++) {
            uint32_t kb = kk * 32;  // bytes (16 bf16)
            uint32_t bh[8], bl[8];
            #pragma unroll
            for (int p = 0; p < 2; p++) {
                int n = wx * 32 + p * 16 + b_nrow;
                uint32_t ah_ = buf + 2 * TILE_B + n * PITCH + kb + b_koff;
                uint32_t al_ = buf + 3 * TILE_B + n * PITCH + kb + b_koff;
                LDSM4(bh[p * 4 + 0], bh[p * 4 + 1], bh[p * 4 + 2], bh[p * 4 + 3], ah_);
                LDSM4(bl[p * 4 + 0], bl[p * 4 + 1], bl[p * 4 + 2], bl[p * 4 + 3], al_);
            }
            #pragma unroll
            for (int mf = 0; mf < 4; mf++) {
                int r = wy * 64 + mf * 16 + a_row;
                uint32_t ah[4];
                LDSM4(ah[0], ah[1], ah[2], ah[3], buf + 0 * TILE_B + r * PITCH + kb + a_koff);
                #pragma unroll
                for (int nf = 0; nf < 4; nf++) {
                    int base = (nf >> 1) * 4 + (nf & 1) * 2;
                    MMA16816(acc[mf][nf], ah, bh[base], bh[base + 1]);  // hi*hi
                    MMA16816(acc[mf][nf], ah, bl[base], bl[base + 1]);  // hi*lo
                }
            }
            #pragma unroll
            for (int mf = 0; mf < 4; mf++) {
                int r = wy * 64 + mf * 16 + a_row;
                uint32_t al[4];
                LDSM4(al[0], al[1], al[2], al[3], buf + 1 * TILE_B + r * PITCH + kb + a_koff);
                #pragma unroll
                for (int nf = 0; nf < 4; nf++) {
                    int base = (nf >> 1) * 4 + (nf & 1) * 2;
                    MMA16816(acc[mf][nf], al, bh[base], bh[base + 1]);  // lo*hi
                }
            }
        }
    }
    __syncthreads();

    // ---- fused epilogue ----
    int liA[8], ljA[8];
    #pragma unroll
    for (int b = 0; b < 8; b++) {
        liA[b] = sLR[wy * 64 + (b >> 1) * 16 + gid + (b & 1) * 8];
        ljA[b] = sLC[wx * 32 + (b >> 1) * 8 + 2 * tig + (b & 1)];
    }
    float rE[8], rW[8], cE[8], cW[8];
    #pragma unroll
    for (int b = 0; b < 8; b++) { rE[b] = 0.f; rW[b] = 0.f; cE[b] = 0.f; cW[b] = 0.f; }

    #pragma unroll
    for (int mf = 0; mf < 4; mf++)
        #pragma unroll
        for (int nf = 0; nf < 4; nf++)
            #pragma unroll
            for (int e = 0; e < 4; e++) {
                int h = e >> 1, q = e & 1;
                int rowloc = wy * 64 + mf * 16 + gid + h * 8;
                int colloc = wx * 32 + nf * 8 + 2 * tig + q;
                float l = acc[mf][nf][e] * LSCALE;
                float ex = __expf(l - LSCALE);
                int li = liA[mf * 2 + h], lj = ljA[nf * 2 + q];
                bool tm = (bm + rowloc == bn + colloc) || (li >= 0 && li == lj);
                float w = tm ? l : 0.f;
                rE[mf * 2 + h] += ex; rW[mf * 2 + h] += w;
                cE[nf * 2 + q] += ex; cW[nf * 2 + q] += w;
            }

    #pragma unroll
    for (int m = 1; m < 4; m <<= 1)
        #pragma unroll
        for (int b = 0; b < 8; b++) {
            rE[b] += __shfl_xor_sync(0xffffffffu, rE[b], m);
            rW[b] += __shfl_xor_sync(0xffffffffu, rW[b], m);
        }
    if (tig == 0) {
        #pragma unroll
        for (int b = 0; b < 8; b++)
            atomicAdd(&sRE[wy * 64 + (b >> 1) * 16 + gid + (b & 1) * 8], rE[b]);
    } else if (tig == 1) {
        #pragma unroll
        for (int b = 0; b < 8; b++)
            atomicAdd(&sRW[wy * 64 + (b >> 1) * 16 + gid + (b & 1) * 8], rW[b]);
    }

    #pragma unroll
    for (int m = 4; m < 32; m <<= 1)
        #pragma unroll
        for (int b = 0; b < 8; b++) {
            cE[b] += __shfl_xor_sync(0xffffffffu, cE[b], m);
            cW[b] += __shfl_xor_sync(0xffffffffu, cW[b], m);
        }
    if (gid == 0) {
        #pragma unroll
        for (int b = 0; b < 8; b++)
            atomicAdd(&sCE[wx * 32 + (b >> 1) * 8 + 2 * tig + (b & 1)], cE[b]);
    } else if (gid == 1) {
        #pragma unroll
        for (int b = 0; b < 8; b++)
            atomicAdd(&sCW[wx * 32 + (b >> 1) * 8 + 2 * tig + (b & 1)], cW[b]);
    }
    __syncthreads();

    if (tid < 128) {
        atomicAdd(&g_rowE[bm + tid], sRE[tid]);
        atomicAdd(&g_rowW[bm + tid], sRW[tid]);
    } else {
        int c = tid - 128;
        atomicAdd(&g_colE[bn + c], sCE[c]);
        atomicAdd(&g_colW[bn + c], sCW[c]);
    }
}

// ---------------------------------------------------------------------------
__global__ void k_final(float* __restrict__ out) {
    int t = threadIdx.x;
    float s = 0.f;
    for (int i = t; i < NN; i += 256) {
        float si = g_Sinv[i];
        float li = logf(g_rowE[i]) + LSCALE - g_rowW[i] * si;
        float lt = logf(g_colE[i]) + LSCALE - g_colW[i] * si;
        s += 0.5f * (li + lt);
    }
    __shared__ float red[256];
    red[t] = s;
    __syncthreads();
    for (int m = 128; m; m >>= 1) {
        if (t < m) red[t] += red[t + m];
        __syncthreads();
    }
    if (t == 0) out[0] = red[0] / (float)NN;
}

// ---------------------------------------------------------------------------
extern "C" void kernel_launch(void* const* d_in, const int* in_sizes, int n_in,
                              void* d_out, int out_size) {
    const float* txt = (const float*)d_in[0];
    const float* img = (const float*)d_in[1];
    const int* labels = (const int*)d_in[2];
    float* out = (float*)d_out;

    static int smem_set = 0;
    if (!smem_set) {
        cudaFuncSetAttribute(k_gemm_mma, cudaFuncAttributeMaxDynamicSharedMemorySize, SMEM_TOT);
        smem_set = 1;
    }

    k_init<<<(NN + 255) / 256, 256>>>();
    k_norm<<<2 * NN, 128>>>(txt, img);
    k_lab<<<(NN + 255) / 256, 256>>>(labels);
    k_S<<<(NN + 255) / 256, 256>>>();
    dim3 g(NN / 128, NN / 128);
    k_gemm_mma<<<g, 256, SMEM_TOT>>>();
    k_final<<<1, 256>>>(out);
}

// round 6
// speedup vs baseline: 5.6352x; 2.2661x over previous
#include <cuda_runtime.h>
#include <cuda_bf16.h>
#include <cstdint>

#define NN 8192
#define DD 512
#define LSCALE 2.659f

// ---------------- device scratch ----------------
__device__ __align__(128) __nv_bfloat16 g_A[NN * DD];   // normalized img, bf16
__device__ __align__(128) __nv_bfloat16 g_B[NN * DD];   // normalized txt, bf16
__device__ float g_rowE[NN], g_rowW[NN], g_colE[NN], g_colW[NN];
__device__ float g_Sinv[NN];
__device__ int   g_lab[NN];
__device__ int   g_hist[128];

// ---------------- asm helpers ----------------
__device__ __forceinline__ uint32_t smem_u32(const void* p) {
    uint32_t a;
    asm("{ .reg .u64 t; cvta.to.shared.u64 t, %1; cvt.u32.u64 %0, t; }" : "=r"(a) : "l"(p));
    return a;
}
#define CP_ASYNC16(dst, src) \
    asm volatile("cp.async.cg.shared.global [%0], [%1], 16;" :: "r"(dst), "l"(src) : "memory")
#define CP_COMMIT() asm volatile("cp.async.commit_group;" ::: "memory")
#define CP_WAIT1()  asm volatile("cp.async.wait_group 1;" ::: "memory")
#define CP_WAIT0()  asm volatile("cp.async.wait_group 0;" ::: "memory")

#define LDSM4(r0, r1, r2, r3, addr) \
    asm volatile("ldmatrix.sync.aligned.m8n8.x4.shared.b16 {%0,%1,%2,%3}, [%4];" \
                 : "=r"(r0), "=r"(r1), "=r"(r2), "=r"(r3) : "r"(addr))

#define MMA16816(d, a, b0, b1) \
    asm volatile("mma.sync.aligned.m16n8k16.row.col.f32.bf16.bf16.f32 " \
                 "{%0,%1,%2,%3}, {%4,%5,%6,%7}, {%8,%9}, {%0,%1,%2,%3};" \
                 : "+f"((d)[0]), "+f"((d)[1]), "+f"((d)[2]), "+f"((d)[3]) \
                 : "r"((a)[0]), "r"((a)[1]), "r"((a)[2]), "r"((a)[3]), "r"(b0), "r"(b1))

// smem tile geometry: rows padded 64B -> 80B (bank-conflict-free ldmatrix)
#define PITCH   80
#define TILE_B  (128 * PITCH)       // 10240 bytes (128 rows x 32 bf16)
#define STAGE_B (2 * TILE_B)        // A + B
#define NSTAGE  3
#define SMEM_RED (NSTAGE * STAGE_B)
#define SMEM_TOT (SMEM_RED + 128 * 4 * 6)

// ---------------------------------------------------------------------------
__global__ void k_init() {
    int i = blockIdx.x * blockDim.x + threadIdx.x;
    if (i < NN) { g_rowE[i] = 0.f; g_rowW[i] = 0.f; g_colE[i] = 0.f; g_colW[i] = 0.f; }
    if (i < 128) g_hist[i] = 0;
}

// normalize -> bf16
__global__ void k_norm(const float* __restrict__ txt, const float* __restrict__ img) {
    int b = blockIdx.x;
    const float* src;
    __nv_bfloat16* dst;
    if (b < NN) { src = img + (size_t)b * DD; dst = g_A + (size_t)b * DD; }
    else { b -= NN; src = txt + (size_t)b * DD; dst = g_B + (size_t)b * DD; }
    int t = threadIdx.x;
    float4 v = ((const float4*)src)[t];
    float ss = v.x * v.x + v.y * v.y + v.z * v.z + v.w * v.w;
    #pragma unroll
    for (int m = 16; m; m >>= 1) ss += __shfl_xor_sync(0xffffffffu, ss, m);
    __shared__ float sp[4];
    if ((t & 31) == 0) sp[t >> 5] = ss;
    __syncthreads();
    float inv = 1.0f / fmaxf(sqrtf(sp[0] + sp[1] + sp[2] + sp[3]), 1e-12f);
    __nv_bfloat162* dp = (__nv_bfloat162*)dst;
    dp[t * 2 + 0] = __nv_bfloat162(__float2bfloat16(v.x * inv), __float2bfloat16(v.y * inv));
    dp[t * 2 + 1] = __nv_bfloat162(__float2bfloat16(v.z * inv), __float2bfloat16(v.w * inv));
}

__global__ void k_lab(const int* __restrict__ labels) {
    int i = blockIdx.x * blockDim.x + threadIdx.x;
    if (i < NN) {
        int l = labels[i];
        if (l < -1 || l >= 128) l = -1;
        g_lab[i] = l;
        if (l >= 0) atomicAdd(&g_hist[l], 1);
    }
}

__global__ void k_S() {
    int i = blockIdx.x * blockDim.x + threadIdx.x;
    if (i < NN) {
        int l = g_lab[i];
        g_Sinv[i] = (l < 0) ? 1.0f : 1.0f / (float)g_hist[l];
    }
}

// ---------------------------------------------------------------------------
// bf16 HMMA GEMM + fused soft-CE epilogue.
// 128x128 tile, 8 warps (2x4), warp tile 64x32, BK=32, 3-stage cp.async pipeline.
__global__ __launch_bounds__(256, 2) void k_gemm_mma() {
    extern __shared__ __align__(16) char smem[];
    uint32_t sb = smem_u32(smem);
    int* sLR = (int*)(smem + SMEM_RED);
    int* sLC = sLR + 128;
    float* sRE = (float*)(sLC + 128);
    float* sRW = sRE + 128;
    float* sCE = sRW + 128;
    float* sCW = sCE + 128;

    int tid = threadIdx.x, lane = tid & 31, wid = tid >> 5;
    int wy = wid >> 2, wx = wid & 3;          // warp grid 2 (m) x 4 (n)
    int gid = lane >> 2, tig = lane & 3;
    int bm = blockIdx.y * 128, bn = blockIdx.x * 128;

    if (tid < 128) {
        sLR[tid] = g_lab[bm + tid]; sLC[tid] = g_lab[bn + tid];
        sRE[tid] = 0.f; sRW[tid] = 0.f; sCE[tid] = 0.f; sCW[tid] = 0.f;
    }

    const __nv_bfloat16* Asrc = g_A + (size_t)bm * DD;
    const __nv_bfloat16* Bsrc = g_B + (size_t)bn * DD;

    auto copy_stage = [&](int it) {
        uint32_t dstb = sb + (uint32_t)(it % NSTAGE) * STAGE_B;
        int k0 = it * 32;
        #pragma unroll
        for (int i = 0; i < 2; i++) {
            int idx = tid + 256 * i;              // 0..511
            int row = idx >> 2, c = idx & 3;      // 4 x 16B per 64B row
            CP_ASYNC16(dstb + row * PITCH + c * 16,
                       Asrc + (size_t)row * DD + k0 + c * 8);
            CP_ASYNC16(dstb + TILE_B + row * PITCH + c * 16,
                       Bsrc + (size_t)row * DD + k0 + c * 8);
        }
        CP_COMMIT();
    };

    float acc[4][4][4];
    #pragma unroll
    for (int mf = 0; mf < 4; mf++)
        #pragma unroll
        for (int nf = 0; nf < 4; nf++)
            #pragma unroll
            for (int e = 0; e < 4; e++) acc[mf][nf][e] = 0.f;

    copy_stage(0);
    copy_stage(1);

    int a_row = (lane & 15);
    uint32_t a_koff = (uint32_t)((lane >> 4) << 4);
    int b_nrow = (lane & 7) + ((lane >> 4) << 3);
    uint32_t b_koff = (uint32_t)(((lane >> 3) & 1) << 4);

    for (int it = 0; it < 16; it++) {
        CP_WAIT1();
        __syncthreads();
        if (it < 14) copy_stage(it + 2);
        else if (it == 15) CP_WAIT0();
        uint32_t buf = sb + (uint32_t)(it % NSTAGE) * STAGE_B;

        #pragma unroll
        for (int kk = 0; kk < 2; kk++) {
            uint32_t kb = kk * 32;  // 16 bf16 in bytes
            uint32_t bh[8];
            #pragma unroll
            for (int p = 0; p < 2; p++) {
                int n = wx * 32 + p * 16 + b_nrow;
                LDSM4(bh[p * 4 + 0], bh[p * 4 + 1], bh[p * 4 + 2], bh[p * 4 + 3],
                      buf + TILE_B + n * PITCH + kb + b_koff);
            }
            #pragma unroll
            for (int mf = 0; mf < 4; mf++) {
                int r = wy * 64 + mf * 16 + a_row;
                uint32_t ah[4];
                LDSM4(ah[0], ah[1], ah[2], ah[3], buf + r * PITCH + kb + a_koff);
                #pragma unroll
                for (int nf = 0; nf < 4; nf++) {
                    int base = (nf >> 1) * 4 + (nf & 1) * 2;
                    MMA16816(acc[mf][nf], ah, bh[base], bh[base + 1]);
                }
            }
        }
    }
    __syncthreads();

    // ---- fused epilogue ----
    int liA[8], ljA[8];
    #pragma unroll
    for (int b = 0; b < 8; b++) {
        liA[b] = sLR[wy * 64 + (b >> 1) * 16 + gid + (b & 1) * 8];
        ljA[b] = sLC[wx * 32 + (b >> 1) * 8 + 2 * tig + (b & 1)];
    }
    float rE[8], rW[8], cE[8], cW[8];
    #pragma unroll
    for (int b = 0; b < 8; b++) { rE[b] = 0.f; rW[b] = 0.f; cE[b] = 0.f; cW[b] = 0.f; }

    #pragma unroll
    for (int mf = 0; mf < 4; mf++)
        #pragma unroll
        for (int nf = 0; nf < 4; nf++)
            #pragma unroll
            for (int e = 0; e < 4; e++) {
                int h = e >> 1, q = e & 1;
                int rowloc = wy * 64 + mf * 16 + gid + h * 8;
                int colloc = wx * 32 + nf * 8 + 2 * tig + q;
                float l = acc[mf][nf][e] * LSCALE;
                float ex = __expf(l - LSCALE);
                int li = liA[mf * 2 + h], lj = ljA[nf * 2 + q];
                bool tm = (bm + rowloc == bn + colloc) || (li >= 0 && li == lj);
                float w = tm ? l : 0.f;
                rE[mf * 2 + h] += ex; rW[mf * 2 + h] += w;
                cE[nf * 2 + q] += ex; cW[nf * 2 + q] += w;
            }

    #pragma unroll
    for (int m = 1; m < 4; m <<= 1)
        #pragma unroll
        for (int b = 0; b < 8; b++) {
            rE[b] += __shfl_xor_sync(0xffffffffu, rE[b], m);
            rW[b] += __shfl_xor_sync(0xffffffffu, rW[b], m);
        }
    if (tig == 0) {
        #pragma unroll
        for (int b = 0; b < 8; b++)
            atomicAdd(&sRE[wy * 64 + (b >> 1) * 16 + gid + (b & 1) * 8], rE[b]);
    } else if (tig == 1) {
        #pragma unroll
        for (int b = 0; b < 8; b++)
            atomicAdd(&sRW[wy * 64 + (b >> 1) * 16 + gid + (b & 1) * 8], rW[b]);
    }

    #pragma unroll
    for (int m = 4; m < 32; m <<= 1)
        #pragma unroll
        for (int b = 0; b < 8; b++) {
            cE[b] += __shfl_xor_sync(0xffffffffu, cE[b], m);
            cW[b] += __shfl_xor_sync(0xffffffffu, cW[b], m);
        }
    if (gid == 0) {
        #pragma unroll
        for (int b = 0; b < 8; b++)
            atomicAdd(&sCE[wx * 32 + (b >> 1) * 8 + 2 * tig + (b & 1)], cE[b]);
    } else if (gid == 1) {
        #pragma unroll
        for (int b = 0; b < 8; b++)
            atomicAdd(&sCW[wx * 32 + (b >> 1) * 8 + 2 * tig + (b & 1)], cW[b]);
    }
    __syncthreads();

    if (tid < 128) {
        atomicAdd(&g_rowE[bm + tid], sRE[tid]);
        atomicAdd(&g_rowW[bm + tid], sRW[tid]);
    } else {
        int c = tid - 128;
        atomicAdd(&g_colE[bn + c], sCE[c]);
        atomicAdd(&g_colW[bn + c], sCW[c]);
    }
}

// ---------------------------------------------------------------------------
__global__ void k_final(float* __restrict__ out) {
    int t = threadIdx.x;
    float s = 0.f;
    for (int i = t; i < NN; i += 256) {
        float si = g_Sinv[i];
        float li = logf(g_rowE[i]) + LSCALE - g_rowW[i] * si;
        float lt = logf(g_colE[i]) + LSCALE - g_colW[i] * si;
        s += 0.5f * (li + lt);
    }
    __shared__ float red[256];
    red[t] = s;
    __syncthreads();
    for (int m = 128; m; m >>= 1) {
        if (t < m) red[t] += red[t + m];
        __syncthreads();
    }
    if (t == 0) out[0] = red[0] / (float)NN;
}

// ---------------------------------------------------------------------------
extern "C" void kernel_launch(void* const* d_in, const int* in_sizes, int n_in,
                              void* d_out, int out_size) {
    const float* txt = (const float*)d_in[0];
    const float* img = (const float*)d_in[1];
    const int* labels = (const int*)d_in[2];
    float* out = (float*)d_out;

    static int smem_set = 0;
    if (!smem_set) {
        cudaFuncSetAttribute(k_gemm_mma, cudaFuncAttributeMaxDynamicSharedMemorySize, SMEM_TOT);
        smem_set = 1;
    }

    k_init<<<(NN + 255) / 256, 256>>>();
    k_norm<<<2 * NN, 128>>>(txt, img);
    k_lab<<<(NN + 255) / 256, 256>>>(labels);
    k_S<<<(NN + 255) / 256, 256>>>();
    dim3 g(NN / 128, NN / 128);
    k_gemm_mma<<<g, 256, SMEM_TOT>>>();
    k_final<<<1, 256>>>(out);
}